// round 2
// baseline (speedup 1.0000x reference)
#include <cuda_runtime.h>

// ---------------- device scratch (no allocations allowed) ----------------
__device__ float g_Upp[128*64*128];   // xT @ W1[:32] + b1   (PP receiver part)
__device__ float g_Vpp[128*64*128];   // xT @ W1[32:64]      (PP sender part)
__device__ float g_Upv[128*64*128];   // xT @ W1pv[:32] + b1pv
__device__ float g_Vpv[128*14*128];   // yT @ W1pv[32:46]
__device__ float g_Epp[128*64*64];    // Ebar_pp
__device__ float g_Epv[128*64*64];    // Ebar_pv

// =====================================================================
// Shared-memory tiled GEMM: Out[64][COLS] = relu(A[64][K] @ W[K][COLS] + bias)
// 256 threads; thread (ty,tx) computes 4 rows x (COLS/16) cols.
// A in shared (row stride lda), W streamed from global in 16-row chunks.
// =====================================================================
template<int K, int COLS>
__device__ __forceinline__ void gemm64(const float* As, int lda,
                                       const float* __restrict__ Wg,
                                       const float* __restrict__ bias,
                                       float* Os, int ldo, float* Wc, int tid)
{
    constexpr int CPT = COLS / 16;         // 8 or 4 cols per thread
    const int ty = tid >> 4, tx = tid & 15;
    float acc[4][CPT];
#pragma unroll
    for (int i = 0; i < 4; i++)
#pragma unroll
        for (int j = 0; j < CPT; j++) acc[i][j] = 0.f;

    for (int k0 = 0; k0 < K; k0 += 16) {
        // stage 16 x COLS chunk of W (coalesced)
        for (int idx = tid; idx < 16 * COLS; idx += 256)
            Wc[idx] = Wg[(k0 + idx / COLS) * COLS + (idx % COLS)];
        __syncthreads();
#pragma unroll
        for (int kk = 0; kk < 16; kk++) {
            float a0 = As[(ty * 4 + 0) * lda + k0 + kk];
            float a1 = As[(ty * 4 + 1) * lda + k0 + kk];
            float a2 = As[(ty * 4 + 2) * lda + k0 + kk];
            float a3 = As[(ty * 4 + 3) * lda + k0 + kk];
            float w[CPT];
            *reinterpret_cast<float4*>(&w[0]) =
                *reinterpret_cast<const float4*>(&Wc[kk * COLS + tx * CPT]);
            if constexpr (CPT == 8)
                *reinterpret_cast<float4*>(&w[4]) =
                    *reinterpret_cast<const float4*>(&Wc[kk * COLS + tx * CPT + 4]);
#pragma unroll
            for (int j = 0; j < CPT; j++) {
                acc[0][j] = fmaf(a0, w[j], acc[0][j]);
                acc[1][j] = fmaf(a1, w[j], acc[1][j]);
                acc[2][j] = fmaf(a2, w[j], acc[2][j]);
                acc[3][j] = fmaf(a3, w[j], acc[3][j]);
            }
        }
        __syncthreads();
    }
#pragma unroll
    for (int j = 0; j < CPT; j++) {
        int c = tx * CPT + j;
        float bv = bias[c];
#pragma unroll
        for (int i = 0; i < 4; i++)
            Os[(ty * 4 + i) * ldo + c] = fmaxf(acc[i][j] + bv, 0.f);
    }
    __syncthreads();
}

// =====================================================================
// Kernel 1: factorized first layers (U/V for PP, U/V for PV)
// one block per b, 256 threads
// =====================================================================
__global__ void precompute_kernel(const float* __restrict__ x, const float* __restrict__ y,
                                  const float* __restrict__ w1,   const float* __restrict__ b1,
                                  const float* __restrict__ w1pv, const float* __restrict__ b1pv)
{
    __shared__ float xs[32][65];           // xs[p][n]
    const int b = blockIdx.x, tid = threadIdx.x;
    for (int idx = tid; idx < 2048; idx += 256) {
        int p = idx >> 6, n = idx & 63;
        xs[p][n] = x[(b * 32 + p) * 64 + n];
    }
    __syncthreads();
    for (int idx = tid; idx < 8192; idx += 256) {
        int n = idx >> 7, h = idx & 127;
        float u = b1[h], v = 0.f, upv = b1pv[h];
#pragma unroll
        for (int p = 0; p < 32; p++) {
            float xv = xs[p][n];
            u   = fmaf(xv, w1[p * 128 + h], u);
            v   = fmaf(xv, w1[(32 + p) * 128 + h], v);
            upv = fmaf(xv, w1pv[p * 128 + h], upv);
        }
        g_Upp[(b * 64 + n) * 128 + h] = u;
        g_Vpp[(b * 64 + n) * 128 + h] = v;
        g_Upv[(b * 64 + n) * 128 + h] = upv;
    }
    for (int idx = tid; idx < 1792; idx += 256) {
        int v = idx >> 7, h = idx & 127;
        float s = 0.f;
#pragma unroll
        for (int sv = 0; sv < 14; sv++)
            s = fmaf(y[(b * 14 + sv) * 14 + v], w1pv[(32 + sv) * 128 + h], s);
        g_Vpv[(b * 14 + v) * 128 + h] = s;
    }
}

// =====================================================================
// Kernel 2: PP edge MLP layers 2+3, fused with receiver scatter-sum.
// block = (r, b): 64 senders (slot s==r computed but excluded from sum).
// =====================================================================
__global__ void pp_kernel(const float* __restrict__ w2, const float* __restrict__ b2,
                          const float* __restrict__ w3, const float* __restrict__ b3)
{
    extern __shared__ float sm[];
    float* h1 = sm;                 // 64 x 132
    float* h2 = sm + 64 * 132;      // 64 x 132
    float* Wc = sm + 2 * 64 * 132;  // 16 x 128
    const int r = blockIdx.x, b = blockIdx.y, tid = threadIdx.x;
    const float* U = &g_Upp[(b * 64 + r) * 128];
    for (int idx = tid; idx < 8192; idx += 256) {
        int s = idx >> 7, k = idx & 127;
        h1[s * 132 + k] = fmaxf(U[k] + g_Vpp[(b * 64 + s) * 128 + k], 0.f);
    }
    __syncthreads();
    gemm64<128, 128>(h1, 132, w2, b2, h2, 132, Wc, tid);
    gemm64<128, 64>(h2, 132, w3, b3, h1, 68, Wc, tid);   // h3 -> h1 buffer
    if (tid < 64) {
        float s = 0.f;
        for (int e = 0; e < 64; e++)
            if (e != r) s += h1[e * 68 + tid];
        g_Epp[(b * 64 + r) * 64 + tid] = s;
    }
}

// =====================================================================
// Kernel 3: PV edge MLP layers 2+3, fused with receiver scatter-sum.
// block = (kg, b): 4 receivers x 14 vertices = 56 edges (rows 56..63 dummy).
// =====================================================================
__global__ void pv_kernel(const float* __restrict__ w2, const float* __restrict__ b2,
                          const float* __restrict__ w3, const float* __restrict__ b3)
{
    extern __shared__ float sm[];
    float* h1 = sm;
    float* h2 = sm + 64 * 132;
    float* Wc = sm + 2 * 64 * 132;
    const int kg = blockIdx.x, b = blockIdx.y, tid = threadIdx.x;
    for (int idx = tid; idx < 8192; idx += 256) {
        int row = idx >> 7, c = idx & 127;
        float val = 0.f;
        if (row < 56) {
            int ki = row / 14;
            int v  = row - ki * 14;
            int kk = kg * 4 + ki;
            val = fmaxf(g_Upv[(b * 64 + kk) * 128 + c] + g_Vpv[(b * 14 + v) * 128 + c], 0.f);
        }
        h1[row * 132 + c] = val;
    }
    __syncthreads();
    gemm64<128, 128>(h1, 132, w2, b2, h2, 132, Wc, tid);
    gemm64<128, 64>(h2, 132, w3, b3, h1, 68, Wc, tid);   // h3 -> h1 buffer
    {
        int col = tid & 63, rg = tid >> 6;   // 4 receivers x 64 cols = 256 threads
        float s = 0.f;
#pragma unroll
        for (int v = 0; v < 14; v++) s += h1[(rg * 14 + v) * 68 + col];
        g_Epv[(b * 64 + kg * 4 + rg) * 64 + col] = s;
    }
}

// =====================================================================
// Kernel 4: object MLP + pool + classifier. one block per b.
// =====================================================================
__global__ void obj_kernel(const float* __restrict__ x,
                           const float* __restrict__ w1, const float* __restrict__ b1,
                           const float* __restrict__ w2, const float* __restrict__ b2,
                           const float* __restrict__ w3, const float* __restrict__ b3,
                           const float* __restrict__ fcw, const float* __restrict__ fcb,
                           float* __restrict__ out)
{
    extern __shared__ float sm[];
    float* C  = sm;                  // 64 x 164
    float* o1 = sm + 64 * 164;       // 64 x 132
    float* o2 = o1 + 64 * 132;       // 64 x 132
    float* Wc = o2 + 64 * 132;       // 16 x 128
    __shared__ float pooled[64];
    const int b = blockIdx.x, tid = threadIdx.x;
    for (int idx = tid; idx < 64 * 160; idx += 256) {
        int n = idx / 160, c = idx - n * 160;
        float v;
        if (c < 32)      v = x[(b * 32 + c) * 64 + n];          // xT[n][c]
        else if (c < 96) v = g_Epp[(b * 64 + n) * 64 + (c - 32)];
        else             v = g_Epv[(b * 64 + n) * 64 + (c - 96)];
        C[n * 164 + c] = v;
    }
    __syncthreads();
    gemm64<160, 128>(C, 164, w1, b1, o1, 132, Wc, tid);
    gemm64<128, 128>(o1, 132, w2, b2, o2, 132, Wc, tid);
    gemm64<128, 64>(o2, 132, w3, b3, C, 68, Wc, tid);    // o3 -> C buffer
    if (tid < 64) {
        float s = 0.f;
        for (int n = 0; n < 64; n++) s += C[n * 68 + tid];
        pooled[tid] = s;
    }
    __syncthreads();
    if (tid < 5) {
        float s = fcb[tid];
        for (int j = 0; j < 64; j++) s = fmaf(pooled[j], fcw[j * 5 + tid], s);
        out[b * 5 + tid] = s;
    }
}

// =====================================================================
extern "C" void kernel_launch(void* const* d_in, const int* in_sizes, int n_in,
                              void* d_out, int out_size)
{
    const float* x       = (const float*)d_in[0];
    const float* y       = (const float*)d_in[1];
    const float* fr1_w   = (const float*)d_in[2];
    const float* fr1_b   = (const float*)d_in[3];
    const float* fr2_w   = (const float*)d_in[4];
    const float* fr2_b   = (const float*)d_in[5];
    const float* fr3_w   = (const float*)d_in[6];
    const float* fr3_b   = (const float*)d_in[7];
    const float* fr1pv_w = (const float*)d_in[8];
    const float* fr1pv_b = (const float*)d_in[9];
    const float* fr2pv_w = (const float*)d_in[10];
    const float* fr2pv_b = (const float*)d_in[11];
    const float* fr3pv_w = (const float*)d_in[12];
    const float* fr3pv_b = (const float*)d_in[13];
    const float* fo1_w   = (const float*)d_in[14];
    const float* fo1_b   = (const float*)d_in[15];
    const float* fo2_w   = (const float*)d_in[16];
    const float* fo2_b   = (const float*)d_in[17];
    const float* fo3_w   = (const float*)d_in[18];
    const float* fo3_b   = (const float*)d_in[19];
    const float* fc_w    = (const float*)d_in[20];
    const float* fc_b    = (const float*)d_in[21];
    float* out = (float*)d_out;

    const int SM_EDGE = (2 * 64 * 132 + 16 * 128) * (int)sizeof(float);   // 75776 B
    const int SM_OBJ  = (64 * 164 + 2 * 64 * 132 + 16 * 128) * (int)sizeof(float); // 117760 B
    cudaFuncSetAttribute(pp_kernel,  cudaFuncAttributeMaxDynamicSharedMemorySize, SM_EDGE);
    cudaFuncSetAttribute(pv_kernel,  cudaFuncAttributeMaxDynamicSharedMemorySize, SM_EDGE);
    cudaFuncSetAttribute(obj_kernel, cudaFuncAttributeMaxDynamicSharedMemorySize, SM_OBJ);

    precompute_kernel<<<128, 256>>>(x, y, fr1_w, fr1_b, fr1pv_w, fr1pv_b);
    pp_kernel<<<dim3(64, 128), 256, SM_EDGE>>>(fr2_w, fr2_b, fr3_w, fr3_b);
    pv_kernel<<<dim3(16, 128), 256, SM_EDGE>>>(fr2pv_w, fr2pv_b, fr3pv_w, fr3pv_b);
    obj_kernel<<<128, 256, SM_OBJ>>>(x, fo1_w, fo1_b, fo2_w, fo2_b,
                                     fo3_w, fo3_b, fc_w, fc_b, out);
}

// round 5
// speedup vs baseline: 2.1431x; 2.1431x over previous
#include <cuda_runtime.h>
#include <cuda_bf16.h>
#include <stdint.h>

#define DI __device__ __forceinline__

// ===================== device scratch (no allocations) =====================
__device__ float g_Upp[128*64*128];
__device__ float g_Vpp[128*64*128];
__device__ float g_Upv[128*64*128];
__device__ float g_Vpv[128*14*128];
__device__ float g_Epp[128*64*64];
__device__ float g_Epv[128*64*64];

// pre-transposed tf32-rounded fp32 weight images: [N][K] k-major, padded stride
__device__ __align__(16) float g_W2pp[128*132];
__device__ __align__(16) float g_W3pp[64*132];
__device__ __align__(16) float g_W2pv[128*132];
__device__ __align__(16) float g_W3pv[64*132];
__device__ __align__(16) float g_FO1 [128*164];   // K=160 (+4 pad)
__device__ __align__(16) float g_FO2 [128*132];
__device__ __align__(16) float g_FO3 [64*132];

// ===================== tf32 helpers =====================
DI float to_tf32(float x){
    float r; asm("cvt.rna.tf32.f32 %0, %1;" : "=f"(r) : "f"(x)); return r;
}
DI void mma_tf32(float* d, uint32_t a0, uint32_t a1, uint32_t a2, uint32_t a3,
                 uint32_t b0, uint32_t b1){
    asm volatile(
        "mma.sync.aligned.m16n8k8.row.col.f32.tf32.tf32.f32 "
        "{%0,%1,%2,%3}, {%4,%5,%6,%7}, {%8,%9}, {%0,%1,%2,%3};"
        : "+f"(d[0]), "+f"(d[1]), "+f"(d[2]), "+f"(d[3])
        : "r"(a0), "r"(a1), "r"(a2), "r"(a3), "r"(b0), "r"(b1));
}

// Warp GEMM: D[16 x N] += A[row0..row0+16][K] @ W[N][K]^T   (tf32, fp32 accum)
// A,W fp32(tf32-rounded) in smem, row strides sa,sw (elements), strides ≡ 4 mod 32.
template<int K, int N>
DI void wgemm32(const float* A, int sa, const float* W, int sw,
                int row0, int lane, float* acc)
{
    const int g = lane >> 2, tg = lane & 3;
#pragma unroll
    for (int i = 0; i < (N/8)*4; i++) acc[i] = 0.f;
    const uint32_t* Au = (const uint32_t*)A;
    const uint32_t* Wu = (const uint32_t*)W;
#pragma unroll 4
    for (int kt = 0; kt < K/8; kt++){
        const int k0 = kt*8 + tg;
        uint32_t a0 = Au[(row0+g)*sa + k0];
        uint32_t a1 = Au[(row0+g+8)*sa + k0];
        uint32_t a2 = Au[(row0+g)*sa + k0 + 4];
        uint32_t a3 = Au[(row0+g+8)*sa + k0 + 4];
#pragma unroll
        for (int nt = 0; nt < N/8; nt++){
            uint32_t b0 = Wu[(nt*8+g)*sw + k0];
            uint32_t b1 = Wu[(nt*8+g)*sw + k0 + 4];
            mma_tf32(acc + nt*4, a0, a1, a2, a3, b0, b1);
        }
    }
}

// Epilogue: relu(acc+bias) -> tf32-rounded fp32 in O (stride so)
template<int N>
DI void epi_store32(const float* acc, float* O, int so,
                    int row0, int lane, const float* bias)
{
    const int g = lane >> 2, tg = lane & 3;
#pragma unroll
    for (int nt = 0; nt < N/8; nt++){
        int c = nt*8 + tg*2;
        float b0 = bias[c], b1 = bias[c+1];
        float2 v0, v1;
        v0.x = to_tf32(fmaxf(acc[nt*4+0]+b0, 0.f));
        v0.y = to_tf32(fmaxf(acc[nt*4+1]+b1, 0.f));
        v1.x = to_tf32(fmaxf(acc[nt*4+2]+b0, 0.f));
        v1.y = to_tf32(fmaxf(acc[nt*4+3]+b1, 0.f));
        *(float2*)(O + (row0+g)*so + c)   = v0;
        *(float2*)(O + (row0+g+8)*so + c) = v1;
    }
}

// ===================== prep: transpose + tf32-round weight images =====================
__global__ void prep_kernel(const float* __restrict__ w2pp, const float* __restrict__ w3pp,
                            const float* __restrict__ w2pv, const float* __restrict__ w3pv,
                            const float* __restrict__ w1o,  const float* __restrict__ w2o,
                            const float* __restrict__ w3o)
{
    int T = blockDim.x * gridDim.x, t0 = blockIdx.x * blockDim.x + threadIdx.x;
    for (int i = t0; i < 128*128; i += T){ int n = i>>7, k = i&127;
        g_W2pp[n*132+k] = to_tf32(w2pp[k*128+n]); }
    for (int i = t0; i < 64*128; i += T){ int n = i>>7, k = i&127;
        g_W3pp[n*132+k] = to_tf32(w3pp[k*64+n]); }
    for (int i = t0; i < 128*128; i += T){ int n = i>>7, k = i&127;
        g_W2pv[n*132+k] = to_tf32(w2pv[k*128+n]); }
    for (int i = t0; i < 64*128; i += T){ int n = i>>7, k = i&127;
        g_W3pv[n*132+k] = to_tf32(w3pv[k*64+n]); }
    for (int i = t0; i < 128*160; i += T){ int n = i/160, k = i - n*160;
        g_FO1[n*164+k] = to_tf32(w1o[k*128+n]); }
    for (int i = t0; i < 128*128; i += T){ int n = i>>7, k = i&127;
        g_FO2[n*132+k] = to_tf32(w2o[k*128+n]); }
    for (int i = t0; i < 64*128; i += T){ int n = i>>7, k = i&127;
        g_FO3[n*132+k] = to_tf32(w3o[k*64+n]); }
}

// ===================== precompute: factorized first layers (fp32) =====================
__global__ void precompute_kernel(const float* __restrict__ x, const float* __restrict__ y,
                                  const float* __restrict__ w1,   const float* __restrict__ b1,
                                  const float* __restrict__ w1pv, const float* __restrict__ b1pv)
{
    __shared__ float xs[32][65];
    const int b = blockIdx.x, tid = threadIdx.x;
    for (int idx = tid; idx < 2048; idx += 256){
        int p = idx >> 6, n = idx & 63;
        xs[p][n] = x[(b*32 + p)*64 + n];
    }
    __syncthreads();
    for (int idx = tid; idx < 8192; idx += 256){
        int n = idx >> 7, h = idx & 127;
        float u = b1[h], v = 0.f, upv = b1pv[h];
#pragma unroll
        for (int p = 0; p < 32; p++){
            float xv = xs[p][n];
            u   = fmaf(xv, w1[p*128 + h], u);
            v   = fmaf(xv, w1[(32+p)*128 + h], v);
            upv = fmaf(xv, w1pv[p*128 + h], upv);
        }
        g_Upp[(b*64+n)*128 + h] = u;
        g_Vpp[(b*64+n)*128 + h] = v;
        g_Upv[(b*64+n)*128 + h] = upv;
    }
    for (int idx = tid; idx < 1792; idx += 256){
        int v = idx >> 7, h = idx & 127;
        float s = 0.f;
#pragma unroll
        for (int sv = 0; sv < 14; sv++)
            s = fmaf(y[(b*14+sv)*14 + v], w1pv[(32+sv)*128 + h], s);
        g_Vpv[(b*14+v)*128 + h] = s;
    }
}

// ===================== PP / PV shared smem map (bytes) =====================
// H1[128x132 f32] | W2[128x132] (H2 overlays after L2) | W3[64x132] | bias2 | bias3 | part
#define E_H1 0
#define E_W2 67584
#define E_W3 135168
#define E_B2 168960
#define E_B3 169472
#define E_PT 169728
#define E_SM 171776

// ===================== PP edges: 2 receivers per block =====================
__global__ __launch_bounds__(256) void pp_kernel(const float* __restrict__ b2v,
                                                 const float* __restrict__ b3v)
{
    extern __shared__ char sm[];
    float* H1 = (float*)(sm + E_H1);
    float* W2 = (float*)(sm + E_W2);     // becomes H2 after layer 2
    float* W3 = (float*)(sm + E_W3);
    float* bias2 = (float*)(sm + E_B2);
    float* bias3 = (float*)(sm + E_B3);
    float* part  = (float*)(sm + E_PT);
    const int tid = threadIdx.x, wid = tid >> 5, lane = tid & 31;
    const int gblk = blockIdx.x, b = blockIdx.y;

    for (int i = tid; i < 4224; i += 256) ((float4*)W2)[i] = ((const float4*)g_W2pp)[i];
    for (int i = tid; i < 2112; i += 256) ((float4*)W3)[i] = ((const float4*)g_W3pp)[i];
    if (tid < 128) bias2[tid] = b2v[tid];
    if (tid < 64)  bias3[tid] = b3v[tid];
    // H1[rl*64+s][k] = tf32(relu(U[2g+rl][k] + V[s][k]))
    for (int i = tid; i < 8192; i += 256){
        int row = i >> 6, k = (i & 63) * 2;
        int rl = row >> 6, s = row & 63;
        const float* U = g_Upp + (b*64 + 2*gblk + rl)*128;
        const float* V = g_Vpp + (b*64 + s)*128;
        float2 v;
        v.x = to_tf32(fmaxf(U[k]   + V[k],   0.f));
        v.y = to_tf32(fmaxf(U[k+1] + V[k+1], 0.f));
        *(float2*)(H1 + row*132 + k) = v;
    }
    __syncthreads();

    {   // layer 2
        float acc[64];
        wgemm32<128,128>(H1, 132, W2, 132, 16*wid, lane, acc);
        __syncthreads();                       // all W2 reads done
        epi_store32<128>(acc, W2, 132, 16*wid, lane, bias2);   // H2 := W2 buffer
    }
    __syncthreads();

    {   // layer 3 + self-excluded column reduction
        float acc[32];
        wgemm32<128,64>(W2, 132, W3, 132, 16*wid, lane, acc);
        const int g = lane >> 2, tg = lane & 3;
        int r1 = 16*wid + g, r2 = r1 + 8;
        bool z1 = ((r1 & 63) == 2*gblk + (r1 >> 6));
        bool z2 = ((r2 & 63) == 2*gblk + (r2 >> 6));
#pragma unroll
        for (int nt = 0; nt < 8; nt++){
            int c = nt*8 + tg*2;
            float b0 = bias3[c], b1 = bias3[c+1];
            float v0 = z1 ? 0.f : fmaxf(acc[nt*4+0]+b0, 0.f);
            float v1 = z1 ? 0.f : fmaxf(acc[nt*4+1]+b1, 0.f);
            float w0 = z2 ? 0.f : fmaxf(acc[nt*4+2]+b0, 0.f);
            float w1 = z2 ? 0.f : fmaxf(acc[nt*4+3]+b1, 0.f);
            float t0 = v0 + w0, t1 = v1 + w1;
#pragma unroll
            for (int m = 4; m < 32; m <<= 1){
                t0 += __shfl_xor_sync(0xffffffffu, t0, m);
                t1 += __shfl_xor_sync(0xffffffffu, t1, m);
            }
            if ((lane >> 2) == 0){ part[wid*64 + c] = t0; part[wid*64 + c + 1] = t1; }
        }
    }
    __syncthreads();
    if (tid < 128){
        int rl = tid >> 6, c = tid & 63;
        float s = part[(4*rl+0)*64+c] + part[(4*rl+1)*64+c]
                + part[(4*rl+2)*64+c] + part[(4*rl+3)*64+c];
        g_Epp[(b*64 + 2*gblk + rl)*64 + c] = s;
    }
}

// ===================== PV edges: 8 receivers x 16 slots per block =====================
__global__ __launch_bounds__(256) void pv_kernel(const float* __restrict__ b2v,
                                                 const float* __restrict__ b3v)
{
    extern __shared__ char sm[];
    float* H1 = (float*)(sm + E_H1);
    float* W2 = (float*)(sm + E_W2);
    float* W3 = (float*)(sm + E_W3);
    float* bias2 = (float*)(sm + E_B2);
    float* bias3 = (float*)(sm + E_B3);
    const int tid = threadIdx.x, wid = tid >> 5, lane = tid & 31;
    const int tile = blockIdx.x, b = blockIdx.y;

    for (int i = tid; i < 4224; i += 256) ((float4*)W2)[i] = ((const float4*)g_W2pv)[i];
    for (int i = tid; i < 2112; i += 256) ((float4*)W3)[i] = ((const float4*)g_W3pv)[i];
    if (tid < 128) bias2[tid] = b2v[tid];
    if (tid < 64)  bias3[tid] = b3v[tid];
    for (int i = tid; i < 8192; i += 256){
        int row = i >> 6, k = (i & 63) * 2;
        int rg = row >> 4, vv = row & 15;
        float2 v; v.x = 0.f; v.y = 0.f;
        if (vv < 14){
            const float* U = g_Upv + (b*64 + tile*8 + rg)*128;
            const float* V = g_Vpv + (b*14 + vv)*128;
            v.x = to_tf32(fmaxf(U[k]   + V[k],   0.f));
            v.y = to_tf32(fmaxf(U[k+1] + V[k+1], 0.f));
        }
        *(float2*)(H1 + row*132 + k) = v;
    }
    __syncthreads();
    {
        float acc[64];
        wgemm32<128,128>(H1, 132, W2, 132, 16*wid, lane, acc);
        __syncthreads();
        epi_store32<128>(acc, W2, 132, 16*wid, lane, bias2);
    }
    __syncthreads();
    {
        float acc[32];
        wgemm32<128,64>(W2, 132, W3, 132, 16*wid, lane, acc);
        const int g = lane >> 2, tg = lane & 3;
        bool z2 = (g >= 6);                       // rows vv = g, g+8 ; pad when g+8 >= 14
        float* dst = &g_Epv[(b*64 + tile*8 + wid)*64];
#pragma unroll
        for (int nt = 0; nt < 8; nt++){
            int c = nt*8 + tg*2;
            float b0 = bias3[c], b1 = bias3[c+1];
            float v0 = fmaxf(acc[nt*4+0]+b0, 0.f);
            float v1 = fmaxf(acc[nt*4+1]+b1, 0.f);
            float w0 = z2 ? 0.f : fmaxf(acc[nt*4+2]+b0, 0.f);
            float w1 = z2 ? 0.f : fmaxf(acc[nt*4+3]+b1, 0.f);
            float t0 = v0 + w0, t1 = v1 + w1;
#pragma unroll
            for (int m = 4; m < 32; m <<= 1){
                t0 += __shfl_xor_sync(0xffffffffu, t0, m);
                t1 += __shfl_xor_sync(0xffffffffu, t1, m);
            }
            if (g == 0){ dst[c] = t0; dst[c+1] = t1; }
        }
    }
}

// ===================== object MLP + pool + classifier: 1 graph/block =====================
// C[64x164] (H3 overlays) | Wbuf[128x164] (FO1->FO2->FO3) | H2[64x132] | misc
#define OB_C   0
#define OB_W   41984
#define OB_H2  125952
#define OB_B1  159744
#define OB_B2  160256
#define OB_B3  160768
#define OB_FCB 161024
#define OB_PL  161088
#define OB_PT  161344
#define OB_SM  163392

__global__ __launch_bounds__(256) void obj_kernel(const float* __restrict__ x,
                                                  const float* __restrict__ b1v,
                                                  const float* __restrict__ b2v,
                                                  const float* __restrict__ b3v,
                                                  const float* __restrict__ fcw,
                                                  const float* __restrict__ fcb,
                                                  float* __restrict__ out)
{
    extern __shared__ char sm[];
    float* C    = (float*)(sm + OB_C);
    float* Wbuf = (float*)(sm + OB_W);
    float* H2   = (float*)(sm + OB_H2);
    float* H3   = (float*)(sm + OB_C);          // overlays C
    float* bias1  = (float*)(sm + OB_B1);
    float* bias2  = (float*)(sm + OB_B2);
    float* bias3  = (float*)(sm + OB_B3);
    float* fcbs   = (float*)(sm + OB_FCB);
    float* pooled = (float*)(sm + OB_PL);
    float* part   = (float*)(sm + OB_PT);
    const int tid = threadIdx.x, wid = tid >> 5, lane = tid & 31;
    const int bg = blockIdx.x;                  // graph
    const int rh = wid >> 1, nh = wid & 1;      // row-group / col-half split

    for (int i = tid; i < 5248; i += 256) ((float4*)Wbuf)[i] = ((const float4*)g_FO1)[i];
    if (tid < 128) bias1[tid] = b1v[tid];
    if (tid < 128) bias2[tid] = b2v[tid];
    if (tid < 64)  bias3[tid] = b3v[tid];
    if (tid < 5)   fcbs[tid]  = fcb[tid];
    // C[n][k], K=160, tf32-rounded
    for (int i = tid; i < 64*80; i += 256){
        int n = i / 80, k = (i - n*80) * 2;
        float v0, v1;
        if (k < 32){      v0 = x[(bg*32 + k)*64 + n]; v1 = x[(bg*32 + k + 1)*64 + n]; }
        else if (k < 96){ const float* e = g_Epp + (bg*64 + n)*64; v0 = e[k-32]; v1 = e[k-31]; }
        else {            const float* e = g_Epv + (bg*64 + n)*64; v0 = e[k-96]; v1 = e[k-95]; }
        float2 v; v.x = to_tf32(v0); v.y = to_tf32(v1);
        *(float2*)(C + n*164 + k) = v;
    }
    __syncthreads();
    {   // layer 1: H2 = relu(C @ FO1^T + b1)   (warps: 4 row groups x 2 col halves)
        float acc[32];
        wgemm32<160,64>(C, 164, Wbuf + nh*64*164, 164, 16*rh, lane, acc);
        epi_store32<64>(acc, H2 + nh*64, 132, 16*rh, lane, bias1 + nh*64);
    }
    __syncthreads();
    for (int i = tid; i < 4224; i += 256) ((float4*)Wbuf)[i] = ((const float4*)g_FO2)[i];
    __syncthreads();
    {   // layer 2: H3 = relu(H2 @ FO2^T + b2)  (H3 overlays C; C is dead)
        float acc[32];
        wgemm32<128,64>(H2, 132, Wbuf + nh*64*132, 132, 16*rh, lane, acc);
        __syncthreads();
        epi_store32<64>(acc, H3 + nh*64, 132, 16*rh, lane, bias2 + nh*64);
    }
    __syncthreads();
    for (int i = tid; i < 2112; i += 256) ((float4*)Wbuf)[i] = ((const float4*)g_FO3)[i];
    __syncthreads();
    {   // layer 3 + pooling reduction (warps: 4 row groups x 2 x 32-col halves)
        float acc[16];
        wgemm32<128,32>(H3, 132, Wbuf + nh*32*132, 132, 16*rh, lane, acc);
        const int g = lane >> 2, tg = lane & 3;
#pragma unroll
        for (int nt = 0; nt < 4; nt++){
            int c = nt*8 + tg*2;
            float b0 = bias3[nh*32 + c], b1 = bias3[nh*32 + c + 1];
            float t0 = fmaxf(acc[nt*4+0]+b0, 0.f) + fmaxf(acc[nt*4+2]+b0, 0.f);
            float t1 = fmaxf(acc[nt*4+1]+b1, 0.f) + fmaxf(acc[nt*4+3]+b1, 0.f);
#pragma unroll
            for (int m = 4; m < 32; m <<= 1){
                t0 += __shfl_xor_sync(0xffffffffu, t0, m);
                t1 += __shfl_xor_sync(0xffffffffu, t1, m);
            }
            if (g == 0){
                part[rh*64 + nh*32 + c]     = t0;
                part[rh*64 + nh*32 + c + 1] = t1;
            }
        }
    }
    __syncthreads();
    if (tid < 64)
        pooled[tid] = part[tid] + part[64+tid] + part[128+tid] + part[192+tid];
    __syncthreads();
    if (tid < 5){
        float s = fcbs[tid];
#pragma unroll 8
        for (int j = 0; j < 64; j++)
            s = fmaf(pooled[j], fcw[j*5 + tid], s);
        out[bg*5 + tid] = s;
    }
}

// ===================== launch =====================
extern "C" void kernel_launch(void* const* d_in, const int* in_sizes, int n_in,
                              void* d_out, int out_size)
{
    const float* x       = (const float*)d_in[0];
    const float* y       = (const float*)d_in[1];
    const float* fr1_w   = (const float*)d_in[2];
    const float* fr1_b   = (const float*)d_in[3];
    const float* fr2_w   = (const float*)d_in[4];
    const float* fr2_b   = (const float*)d_in[5];
    const float* fr3_w   = (const float*)d_in[6];
    const float* fr3_b   = (const float*)d_in[7];
    const float* fr1pv_w = (const float*)d_in[8];
    const float* fr1pv_b = (const float*)d_in[9];
    const float* fr2pv_w = (const float*)d_in[10];
    const float* fr2pv_b = (const float*)d_in[11];
    const float* fr3pv_w = (const float*)d_in[12];
    const float* fr3pv_b = (const float*)d_in[13];
    const float* fo1_w   = (const float*)d_in[14];
    const float* fo1_b   = (const float*)d_in[15];
    const float* fo2_w   = (const float*)d_in[16];
    const float* fo2_b   = (const float*)d_in[17];
    const float* fo3_w   = (const float*)d_in[18];
    const float* fo3_b   = (const float*)d_in[19];
    const float* fc_w    = (const float*)d_in[20];
    const float* fc_b    = (const float*)d_in[21];
    float* out = (float*)d_out;

    cudaFuncSetAttribute(pp_kernel,  cudaFuncAttributeMaxDynamicSharedMemorySize, E_SM);
    cudaFuncSetAttribute(pv_kernel,  cudaFuncAttributeMaxDynamicSharedMemorySize, E_SM);
    cudaFuncSetAttribute(obj_kernel, cudaFuncAttributeMaxDynamicSharedMemorySize, OB_SM);

    prep_kernel<<<64, 256>>>(fr2_w, fr3_w, fr2pv_w, fr3pv_w, fo1_w, fo2_w, fo3_w);
    precompute_kernel<<<128, 256>>>(x, y, fr1_w, fr1_b, fr1pv_w, fr1pv_b);
    pp_kernel<<<dim3(32, 128), 256, E_SM>>>(fr2_b, fr3_b);
    pv_kernel<<<dim3(8, 128), 256, E_SM>>>(fr2pv_b, fr3pv_b);
    obj_kernel<<<128, 256, OB_SM>>>(x, fo1_b, fo2_b, fo3_b, fc_w, fc_b, out);
}

// round 6
// speedup vs baseline: 3.4460x; 1.6080x over previous
#include <cuda_runtime.h>
#include <stdint.h>

#define DI __device__ __forceinline__

// ===================== device scratch (no allocations) =====================
// U/V stored in pair-permuted channel order (see pairpos)
__device__ float g_Upp[128*64*128];
__device__ float g_Vpp[128*64*128];
__device__ float g_Upv[128*64*128];
__device__ float g_Vpv[128*14*128];
__device__ float g_EppT[128*64*64];   // transposed: [b][c][r]
__device__ float g_EpvT[128*64*64];   // transposed: [b][c][r]

// pre-transposed tf32 weight images, pair-permuted k, stride 136 (168 for FO1)
__device__ __align__(16) float g_W2pp[128*136];
__device__ __align__(16) float g_W3pp[64*136];
__device__ __align__(16) float g_W2pv[128*136];
__device__ __align__(16) float g_W3pv[64*136];
__device__ __align__(16) float g_FO1 [128*168];
__device__ __align__(16) float g_FO2 [128*136];
__device__ __align__(16) float g_FO3 [64*136];

// ===================== helpers =====================
DI float to_tf32(float x){ float r; asm("cvt.rna.tf32.f32 %0, %1;" : "=f"(r) : "f"(x)); return r; }
// within pair-permuted layout, channel k lives at float offset pairpos(k):
// group of 8 channels -> pairs (k, k+4) adjacent
DI int pairpos(int k){ return (k & ~7) | (((k & 3) << 1) | ((k >> 2) & 1)); }

DI void mma_tf32(float* d, uint32_t a0, uint32_t a1, uint32_t a2, uint32_t a3,
                 uint32_t b0, uint32_t b1){
    asm volatile(
        "mma.sync.aligned.m16n8k8.row.col.f32.tf32.tf32.f32 "
        "{%0,%1,%2,%3}, {%4,%5,%6,%7}, {%8,%9}, {%0,%1,%2,%3};"
        : "+f"(d[0]), "+f"(d[1]), "+f"(d[2]), "+f"(d[3])
        : "r"(a0), "r"(a1), "r"(a2), "r"(a3), "r"(b0), "r"(b1));
}

// Warp GEMM on pair-interleaved tf32 buffers.
// Warp computes MT m-tiles (16 rows each, at row0, row0+16) x NT n-tiles (8 cols) from ncol0.
// acc[MT*NT*4].  Strides sa, sw in floats, must be ≡ 8 (mod 32).
template<int KT, int MT, int NT>
DI void wgemmp(const float* A, int sa, const float* W, int sw,
               int row0, int ncol0, int lane, float* acc)
{
    const int g = lane >> 2, tg = lane & 3;
#pragma unroll
    for (int i = 0; i < MT*NT*4; i++) acc[i] = 0.f;
#pragma unroll
    for (int kt = 0; kt < KT; kt++){
        const int jo = kt*8 + tg*2;
        float2 av[2*MT];
#pragma unroll
        for (int mt = 0; mt < MT; mt++){
            av[2*mt]   = *(const float2*)(A + (row0 + mt*16 + g)*sa + jo);
            av[2*mt+1] = *(const float2*)(A + (row0 + mt*16 + g + 8)*sa + jo);
        }
#pragma unroll
        for (int nt = 0; nt < NT; nt++){
            float2 bv = *(const float2*)(W + (ncol0 + nt*8 + g)*sw + jo);
#pragma unroll
            for (int mt = 0; mt < MT; mt++)
                mma_tf32(acc + (mt*NT+nt)*4,
                         __float_as_uint(av[2*mt].x),   __float_as_uint(av[2*mt+1].x),
                         __float_as_uint(av[2*mt].y),   __float_as_uint(av[2*mt+1].y),
                         __float_as_uint(bv.x),         __float_as_uint(bv.y));
        }
    }
}

// Epilogue: relu(acc+bias) -> tf32, stored pair-permuted into O (stride so)
template<int MT, int NT>
DI void epi_storep(const float* acc, float* O, int so,
                   int row0, int ncol0, int lane, const float* bias)
{
    const int g = lane >> 2, tg = lane & 3;
    const int p0 = pairpos(2*tg);
    const int p1 = pairpos(2*tg + 1);
#pragma unroll
    for (int mt = 0; mt < MT; mt++){
#pragma unroll
        for (int nt = 0; nt < NT; nt++){
            int cb = ncol0 + nt*8;
            float b0 = bias[cb + 2*tg], b1 = bias[cb + 2*tg + 1];
            const float* a = acc + (mt*NT+nt)*4;
            int r = row0 + mt*16 + g;
            O[r*so + cb + p0]     = to_tf32(fmaxf(a[0]+b0, 0.f));
            O[r*so + cb + p1]     = to_tf32(fmaxf(a[1]+b1, 0.f));
            O[(r+8)*so + cb + p0] = to_tf32(fmaxf(a[2]+b0, 0.f));
            O[(r+8)*so + cb + p1] = to_tf32(fmaxf(a[3]+b1, 0.f));
        }
    }
}

// ===================== prep: transpose + tf32 + pair-permute weights =====================
__global__ void prep_kernel(const float* __restrict__ w2pp, const float* __restrict__ w3pp,
                            const float* __restrict__ w2pv, const float* __restrict__ w3pv,
                            const float* __restrict__ w1o,  const float* __restrict__ w2o,
                            const float* __restrict__ w3o)
{
    int T = blockDim.x * gridDim.x, t0 = blockIdx.x * blockDim.x + threadIdx.x;
    for (int i = t0; i < 128*128; i += T){ int n = i>>7, k = i&127;
        g_W2pp[n*136 + pairpos(k)] = to_tf32(w2pp[k*128+n]); }
    for (int i = t0; i < 64*128; i += T){ int n = i>>7, k = i&127;
        g_W3pp[n*136 + pairpos(k)] = to_tf32(w3pp[k*64+n]); }
    for (int i = t0; i < 128*128; i += T){ int n = i>>7, k = i&127;
        g_W2pv[n*136 + pairpos(k)] = to_tf32(w2pv[k*128+n]); }
    for (int i = t0; i < 64*128; i += T){ int n = i>>7, k = i&127;
        g_W3pv[n*136 + pairpos(k)] = to_tf32(w3pv[k*64+n]); }
    for (int i = t0; i < 128*160; i += T){ int n = i/160, k = i - n*160;
        g_FO1[n*168 + pairpos(k)] = to_tf32(w1o[k*128+n]); }
    for (int i = t0; i < 128*128; i += T){ int n = i>>7, k = i&127;
        g_FO2[n*136 + pairpos(k)] = to_tf32(w2o[k*128+n]); }
    for (int i = t0; i < 64*128; i += T){ int n = i>>7, k = i&127;
        g_FO3[n*136 + pairpos(k)] = to_tf32(w3o[k*64+n]); }
}

// ===================== precompute: factorized first layers (fp32, pair-permuted out) ==========
__global__ void precompute_kernel(const float* __restrict__ x, const float* __restrict__ y,
                                  const float* __restrict__ w1,   const float* __restrict__ b1,
                                  const float* __restrict__ w1pv, const float* __restrict__ b1pv)
{
    __shared__ float xs[32][65];
    const int b = blockIdx.x, tid = threadIdx.x;
    for (int idx = tid; idx < 2048; idx += 256){
        int p = idx >> 6, n = idx & 63;
        xs[p][n] = x[(b*32 + p)*64 + n];
    }
    __syncthreads();
    for (int idx = tid; idx < 8192; idx += 256){
        int n = idx >> 7, h = idx & 127;
        float u = b1[h], v = 0.f, upv = b1pv[h];
#pragma unroll
        for (int p = 0; p < 32; p++){
            float xv = xs[p][n];
            u   = fmaf(xv, w1[p*128 + h], u);
            v   = fmaf(xv, w1[(32+p)*128 + h], v);
            upv = fmaf(xv, w1pv[p*128 + h], upv);
        }
        int ph = pairpos(h);
        g_Upp[(b*64+n)*128 + ph] = u;
        g_Vpp[(b*64+n)*128 + ph] = v;
        g_Upv[(b*64+n)*128 + ph] = upv;
    }
    for (int idx = tid; idx < 1792; idx += 256){
        int v = idx >> 7, h = idx & 127;
        float s = 0.f;
#pragma unroll
        for (int sv = 0; sv < 14; sv++)
            s = fmaf(y[(b*14+sv)*14 + v], w1pv[(32+sv)*128 + h], s);
        g_Vpv[(b*14+v)*128 + pairpos(h)] = s;
    }
}

// ===================== edge kernels: persistent, weights resident =====================
// smem map (bytes): W2[128x136] | W3[64x136] | BUF[128x136] (H1 then H2) | b2 | b3 | part
#define EP_W2  0
#define EP_W3  69632
#define EP_BUF 104448
#define EP_B2  174080
#define EP_B3  174592
#define EP_PT  174848
#define EP_SM  175872

__global__ __launch_bounds__(256, 1) void pp_kernel(const float* __restrict__ b2v,
                                                    const float* __restrict__ b3v)
{
    extern __shared__ char sm[];
    float* W2   = (float*)(sm + EP_W2);
    float* W3   = (float*)(sm + EP_W3);
    float* BUF  = (float*)(sm + EP_BUF);
    float* bias2= (float*)(sm + EP_B2);
    float* bias3= (float*)(sm + EP_B3);
    float* part = (float*)(sm + EP_PT);
    const int tid = threadIdx.x, wid = tid >> 5, lane = tid & 31;
    const int g = lane >> 2, tg = lane & 3;
    const int rg = wid >> 1, cg = wid & 1;

    for (int i = tid; i < 4352; i += 256) ((float4*)W2)[i] = ((const float4*)g_W2pp)[i];
    for (int i = tid; i < 2176; i += 256) ((float4*)W3)[i] = ((const float4*)g_W3pp)[i];
    if (tid < 128) bias2[tid] = b2v[tid];
    if (tid < 64)  bias3[tid] = b3v[tid];
    __syncthreads();

    for (int t = blockIdx.x; t < 4096; t += gridDim.x){
        const int b = t >> 5, gblk = t & 31;
        // build H1[row = rl*64 + s][.] = tf32(relu(U[2gblk+rl] + V[s]))  (pair layout)
        const float* Ub = g_Upp + (b*64 + 2*gblk)*128;
        const float* Vb = g_Vpp + (size_t)b*64*128;
        for (int i = tid; i < 8192; i += 256){
            int row = i >> 6, j = i & 63;
            int rl = row >> 6, s = row & 63;
            int fo = 8*(j >> 2) + 2*(j & 3);
            float2 u = *(const float2*)(Ub + rl*128 + fo);
            float2 v = *(const float2*)(Vb + s*128 + fo);
            float2 h;
            h.x = to_tf32(fmaxf(u.x + v.x, 0.f));
            h.y = to_tf32(fmaxf(u.y + v.y, 0.f));
            *(float2*)(BUF + row*136 + fo) = h;
        }
        __syncthreads();
        {   // layer 2
            float acc[64];
            wgemmp<16,2,8>(BUF, 136, W2, 136, rg*32, cg*64, lane, acc);
            __syncthreads();
            epi_storep<2,8>(acc, BUF, 136, rg*32, cg*64, lane, bias2);
        }
        __syncthreads();
        {   // layer 3 + self-excluded column reduce
            float acc3[32];
            wgemmp<16,2,4>(BUF, 136, W3, 136, rg*32, cg*32, lane, acc3);
#pragma unroll
            for (int nt = 0; nt < 4; nt++){
                int c = cg*32 + nt*8 + tg*2;
                float b0 = bias3[c], b1 = bias3[c+1];
                float t0 = 0.f, t1 = 0.f;
#pragma unroll
                for (int mt = 0; mt < 2; mt++){
                    int r = rg*32 + mt*16 + g;
                    const float* a = acc3 + (mt*4+nt)*4;
                    bool z1 = ((r & 63)      == 2*gblk + (r >> 6));
                    bool z2 = (((r+8) & 63)  == 2*gblk + (r >> 6));
                    t0 += (z1 ? 0.f : fmaxf(a[0]+b0, 0.f)) + (z2 ? 0.f : fmaxf(a[2]+b0, 0.f));
                    t1 += (z1 ? 0.f : fmaxf(a[1]+b1, 0.f)) + (z2 ? 0.f : fmaxf(a[3]+b1, 0.f));
                }
#pragma unroll
                for (int m = 4; m < 32; m <<= 1){
                    t0 += __shfl_xor_sync(0xffffffffu, t0, m);
                    t1 += __shfl_xor_sync(0xffffffffu, t1, m);
                }
                if (g == 0){ part[rg*64 + c] = t0; part[rg*64 + c + 1] = t1; }
            }
        }
        __syncthreads();
        if (tid < 128){
            int rl = tid >> 6, c = tid & 63;
            float s = part[(2*rl)*64 + c] + part[(2*rl+1)*64 + c];
            g_EppT[((size_t)b*64 + c)*64 + (2*gblk + rl)] = s;   // transposed
        }
        __syncthreads();
    }
}

__global__ __launch_bounds__(256, 1) void pv_kernel(const float* __restrict__ b2v,
                                                    const float* __restrict__ b3v)
{
    extern __shared__ char sm[];
    float* W2   = (float*)(sm + EP_W2);
    float* W3   = (float*)(sm + EP_W3);
    float* BUF  = (float*)(sm + EP_BUF);
    float* bias2= (float*)(sm + EP_B2);
    float* bias3= (float*)(sm + EP_B3);
    const int tid = threadIdx.x, wid = tid >> 5, lane = tid & 31;
    const int g = lane >> 2, tg = lane & 3;
    const int rg = wid >> 1, cg = wid & 1;

    for (int i = tid; i < 4352; i += 256) ((float4*)W2)[i] = ((const float4*)g_W2pv)[i];
    for (int i = tid; i < 2176; i += 256) ((float4*)W3)[i] = ((const float4*)g_W3pv)[i];
    if (tid < 128) bias2[tid] = b2v[tid];
    if (tid < 64)  bias3[tid] = b3v[tid];
    __syncthreads();

    for (int t = blockIdx.x; t < 1024; t += gridDim.x){
        const int b = t >> 3, tile = t & 7;
        // H1[row = rg8*16 + vv]: vv<14 -> relu(U[tile*8+rg8] + V[vv]); else 0
        const float* Ub = g_Upv + (b*64 + tile*8)*128;
        const float* Vb = g_Vpv + (size_t)b*14*128;
        for (int i = tid; i < 8192; i += 256){
            int row = i >> 6, j = i & 63;
            int rg8 = row >> 4, vv = row & 15;
            int fo = 8*(j >> 2) + 2*(j & 3);
            float2 h; h.x = 0.f; h.y = 0.f;
            if (vv < 14){
                float2 u = *(const float2*)(Ub + rg8*128 + fo);
                float2 v = *(const float2*)(Vb + vv*128 + fo);
                h.x = to_tf32(fmaxf(u.x + v.x, 0.f));
                h.y = to_tf32(fmaxf(u.y + v.y, 0.f));
            }
            *(float2*)(BUF + row*136 + fo) = h;
        }
        __syncthreads();
        {
            float acc[64];
            wgemmp<16,2,8>(BUF, 136, W2, 136, rg*32, cg*64, lane, acc);
            __syncthreads();
            epi_storep<2,8>(acc, BUF, 136, rg*32, cg*64, lane, bias2);
        }
        __syncthreads();
        {   // layer 3 + per-receiver reduce (receiver = 2rg+mt; rows vv=g valid, vv=g+8 pad when g>=6)
            float acc3[32];
            wgemmp<16,2,4>(BUF, 136, W3, 136, rg*32, cg*32, lane, acc3);
#pragma unroll
            for (int mt = 0; mt < 2; mt++){
                int recv = tile*8 + 2*rg + mt;
#pragma unroll
                for (int nt = 0; nt < 4; nt++){
                    int c = cg*32 + nt*8 + tg*2;
                    float b0 = bias3[c], b1 = bias3[c+1];
                    const float* a = acc3 + (mt*4+nt)*4;
                    bool z2 = (g >= 6);
                    float t0 = fmaxf(a[0]+b0, 0.f) + (z2 ? 0.f : fmaxf(a[2]+b0, 0.f));
                    float t1 = fmaxf(a[1]+b1, 0.f) + (z2 ? 0.f : fmaxf(a[3]+b1, 0.f));
#pragma unroll
                    for (int m = 4; m < 32; m <<= 1){
                        t0 += __shfl_xor_sync(0xffffffffu, t0, m);
                        t1 += __shfl_xor_sync(0xffffffffu, t1, m);
                    }
                    if (g == 0){
                        g_EpvT[((size_t)b*64 + c)*64 + recv]     = t0;   // transposed
                        g_EpvT[((size_t)b*64 + c + 1)*64 + recv] = t1;
                    }
                }
            }
        }
        __syncthreads();
    }
}

// ===================== object MLP + pool + classifier: 1 graph/block =====================
// C[64x168] (H3 overlays at stride 136) | Wbuf[128x168] (FO1->FO2->FO3) | H2[64x136] | misc
#define OB_C   0
#define OB_W   43008
#define OB_H2  129024
#define OB_B1  163840
#define OB_B2  164352
#define OB_B3  164864
#define OB_FCB 165120
#define OB_PT  165152
#define OB_PL  165664
#define OB_SM  165920

__global__ __launch_bounds__(256) void obj_kernel(const float* __restrict__ x,
                                                  const float* __restrict__ b1v,
                                                  const float* __restrict__ b2v,
                                                  const float* __restrict__ b3v,
                                                  const float* __restrict__ fcw,
                                                  const float* __restrict__ fcb,
                                                  float* __restrict__ out)
{
    extern __shared__ char sm[];
    float* C    = (float*)(sm + OB_C);
    float* Wbuf = (float*)(sm + OB_W);
    float* H2   = (float*)(sm + OB_H2);
    float* H3   = (float*)(sm + OB_C);          // overlays C, stride 136
    float* bias1  = (float*)(sm + OB_B1);
    float* bias2  = (float*)(sm + OB_B2);
    float* bias3  = (float*)(sm + OB_B3);
    float* fcbs   = (float*)(sm + OB_FCB);
    float* part   = (float*)(sm + OB_PT);
    float* pooled = (float*)(sm + OB_PL);
    const int tid = threadIdx.x, wid = tid >> 5, lane = tid & 31;
    const int g = lane >> 2, tg = lane & 3;
    const int rg = wid >> 2, cg = wid & 3;     // 2 row-groups x 4 col-groups
    const int bg = blockIdx.x;

    for (int i = tid; i < 5376; i += 256) ((float4*)Wbuf)[i] = ((const float4*)g_FO1)[i];
    if (tid < 128) bias1[tid] = b1v[tid];
    if (tid < 128) bias2[tid] = b2v[tid];
    if (tid < 64)  bias3[tid] = b3v[tid];
    if (tid < 5)   fcbs[tid]  = fcb[tid];
    // C[n][k], K=160, pair-permuted, stride 168
    for (int i = tid; i < 64*80; i += 256){
        int n = i & 63, j = i >> 6;            // j = pair slot 0..79
        int k0 = 8*(j >> 2) + (j & 3);
        int fo = 8*(j >> 2) + 2*(j & 3);
        float v0, v1;
        if (k0 < 32){
            v0 = x[(bg*32 + k0)*64 + n];  v1 = x[(bg*32 + k0 + 4)*64 + n];
        } else if (k0 < 96){
            v0 = g_EppT[((size_t)bg*64 + (k0-32))*64 + n];
            v1 = g_EppT[((size_t)bg*64 + (k0-28))*64 + n];
        } else {
            v0 = g_EpvT[((size_t)bg*64 + (k0-96))*64 + n];
            v1 = g_EpvT[((size_t)bg*64 + (k0-92))*64 + n];
        }
        float2 h; h.x = to_tf32(v0); h.y = to_tf32(v1);
        *(float2*)(C + n*168 + fo) = h;
    }
    __syncthreads();
    {   // layer 1: H2 = relu(C @ FO1^T + b1)
        float acc[32];
        wgemmp<20,2,4>(C, 168, Wbuf, 168, rg*32, cg*32, lane, acc);
        epi_storep<2,4>(acc, H2, 136, rg*32, cg*32, lane, bias1);
    }
    __syncthreads();
    for (int i = tid; i < 4352; i += 256) ((float4*)Wbuf)[i] = ((const float4*)g_FO2)[i];
    __syncthreads();
    {   // layer 2: H3 = relu(H2 @ FO2^T + b2)  (H3 overlays C)
        float acc[32];
        wgemmp<16,2,4>(H2, 136, Wbuf, 136, rg*32, cg*32, lane, acc);
        __syncthreads();
        epi_storep<2,4>(acc, H3, 136, rg*32, cg*32, lane, bias2);
    }
    __syncthreads();
    for (int i = tid; i < 2176; i += 256) ((float4*)Wbuf)[i] = ((const float4*)g_FO3)[i];
    __syncthreads();
    {   // layer 3 + pooling reduce
        float acc[16];
        wgemmp<16,2,2>(H3, 136, Wbuf, 136, rg*32, cg*16, lane, acc);
#pragma unroll
        for (int nt = 0; nt < 2; nt++){
            int c = cg*16 + nt*8 + tg*2;
            float b0 = bias3[c], b1 = bias3[c+1];
            float t0 = 0.f, t1 = 0.f;
#pragma unroll
            for (int mt = 0; mt < 2; mt++){
                const float* a = acc + (mt*2+nt)*4;
                t0 += fmaxf(a[0]+b0, 0.f) + fmaxf(a[2]+b0, 0.f);
                t1 += fmaxf(a[1]+b1, 0.f) + fmaxf(a[3]+b1, 0.f);
            }
#pragma unroll
            for (int m = 4; m < 32; m <<= 1){
                t0 += __shfl_xor_sync(0xffffffffu, t0, m);
                t1 += __shfl_xor_sync(0xffffffffu, t1, m);
            }
            if (g == 0){ part[rg*64 + c] = t0; part[rg*64 + c + 1] = t1; }
        }
    }
    __syncthreads();
    if (tid < 64) pooled[tid] = part[tid] + part[64 + tid];
    __syncthreads();
    if (tid < 5){
        float s = fcbs[tid];
#pragma unroll 8
        for (int j = 0; j < 64; j++)
            s = fmaf(pooled[j], fcw[j*5 + tid], s);
        out[bg*5 + tid] = s;
    }
}

// ===================== launch =====================
extern "C" void kernel_launch(void* const* d_in, const int* in_sizes, int n_in,
                              void* d_out, int out_size)
{
    const float* x       = (const float*)d_in[0];
    const float* y       = (const float*)d_in[1];
    const float* fr1_w   = (const float*)d_in[2];
    const float* fr1_b   = (const float*)d_in[3];
    const float* fr2_w   = (const float*)d_in[4];
    const float* fr2_b   = (const float*)d_in[5];
    const float* fr3_w   = (const float*)d_in[6];
    const float* fr3_b   = (const float*)d_in[7];
    const float* fr1pv_w = (const float*)d_in[8];
    const float* fr1pv_b = (const float*)d_in[9];
    const float* fr2pv_w = (const float*)d_in[10];
    const float* fr2pv_b = (const float*)d_in[11];
    const float* fr3pv_w = (const float*)d_in[12];
    const float* fr3pv_b = (const float*)d_in[13];
    const float* fo1_w   = (const float*)d_in[14];
    const float* fo1_b   = (const float*)d_in[15];
    const float* fo2_w   = (const float*)d_in[16];
    const float* fo2_b   = (const float*)d_in[17];
    const float* fo3_w   = (const float*)d_in[18];
    const float* fo3_b   = (const float*)d_in[19];
    const float* fc_w    = (const float*)d_in[20];
    const float* fc_b    = (const float*)d_in[21];
    float* out = (float*)d_out;

    cudaFuncSetAttribute(pp_kernel,  cudaFuncAttributeMaxDynamicSharedMemorySize, EP_SM);
    cudaFuncSetAttribute(pv_kernel,  cudaFuncAttributeMaxDynamicSharedMemorySize, EP_SM);
    cudaFuncSetAttribute(obj_kernel, cudaFuncAttributeMaxDynamicSharedMemorySize, OB_SM);

    prep_kernel<<<64, 256>>>(fr2_w, fr3_w, fr2pv_w, fr3pv_w, fo1_w, fo2_w, fo3_w);
    precompute_kernel<<<128, 256>>>(x, y, fr1_w, fr1_b, fr1pv_w, fr1pv_b);
    pp_kernel<<<152, 256, EP_SM>>>(fr2_b, fr3_b);
    pv_kernel<<<152, 256, EP_SM>>>(fr2pv_b, fr3pv_b);
    obj_kernel<<<128, 256, OB_SM>>>(x, fo1_b, fo2_b, fo3_b, fc_w, fc_b, out);
}

// round 7
// speedup vs baseline: 4.0713x; 1.1815x over previous
#include <cuda_runtime.h>
#include <stdint.h>

#define DI __device__ __forceinline__

// ===================== device scratch (no allocations) =====================
// U/V stored in pair-permuted channel order (see pairpos)
__device__ float g_Upp[128*64*128];
__device__ float g_Vpp[128*64*128];
__device__ float g_Upv[128*64*128];
__device__ float g_Vpv[128*14*128];
__device__ float g_EppT[128*64*64];   // transposed: [b][c][r]
__device__ float g_EpvT[128*64*64];   // transposed: [b][c][r]

// pre-transposed tf32 weight images, pair-permuted k, stride 136 (168 for FO1)
__device__ __align__(16) float g_W2pp[128*136];
__device__ __align__(16) float g_W3pp[64*136];
__device__ __align__(16) float g_W2pv[128*136];
__device__ __align__(16) float g_W3pv[64*136];
__device__ __align__(16) float g_FO1 [128*168];
__device__ __align__(16) float g_FO2 [128*136];
__device__ __align__(16) float g_FO3 [64*136];

// ===================== helpers =====================
DI float to_tf32(float x){ float r; asm("cvt.rna.tf32.f32 %0, %1;" : "=f"(r) : "f"(x)); return r; }
DI int pairpos(int k){ return (k & ~7) | (((k & 3) << 1) | ((k >> 2) & 1)); }
DI void barh(int id){ asm volatile("bar.sync %0, %1;" :: "r"(id), "r"(256) : "memory"); }

DI void mma_tf32(float* d, uint32_t a0, uint32_t a1, uint32_t a2, uint32_t a3,
                 uint32_t b0, uint32_t b1){
    asm volatile(
        "mma.sync.aligned.m16n8k8.row.col.f32.tf32.tf32.f32 "
        "{%0,%1,%2,%3}, {%4,%5,%6,%7}, {%8,%9}, {%0,%1,%2,%3};"
        : "+f"(d[0]), "+f"(d[1]), "+f"(d[2]), "+f"(d[3])
        : "r"(a0), "r"(a1), "r"(a2), "r"(a3), "r"(b0), "r"(b1));
}

// Warp GEMM on pair-interleaved tf32 buffers.
// MT m-tiles (16 rows, at row0 + mt*16) x NT n-tiles (8 cols from ncol0). acc[MT*NT*4].
template<int KT, int MT, int NT>
DI void wgemmp(const float* A, int sa, const float* W, int sw,
               int row0, int ncol0, int lane, float* acc)
{
    const int g = lane >> 2, tg = lane & 3;
#pragma unroll
    for (int i = 0; i < MT*NT*4; i++) acc[i] = 0.f;
#pragma unroll
    for (int kt = 0; kt < KT; kt++){
        const int jo = kt*8 + tg*2;
        float2 av[2*MT];
#pragma unroll
        for (int mt = 0; mt < MT; mt++){
            av[2*mt]   = *(const float2*)(A + (row0 + mt*16 + g)*sa + jo);
            av[2*mt+1] = *(const float2*)(A + (row0 + mt*16 + g + 8)*sa + jo);
        }
#pragma unroll
        for (int nt = 0; nt < NT; nt++){
            float2 bv = *(const float2*)(W + (ncol0 + nt*8 + g)*sw + jo);
#pragma unroll
            for (int mt = 0; mt < MT; mt++)
                mma_tf32(acc + (mt*NT+nt)*4,
                         __float_as_uint(av[2*mt].x),   __float_as_uint(av[2*mt+1].x),
                         __float_as_uint(av[2*mt].y),   __float_as_uint(av[2*mt+1].y),
                         __float_as_uint(bv.x),         __float_as_uint(bv.y));
        }
    }
}

// Epilogue: relu(acc+bias) -> tf32, stored pair-permuted into O (stride so)
template<int MT, int NT>
DI void epi_storep(const float* acc, float* O, int so,
                   int row0, int ncol0, int lane, const float* bias)
{
    const int g = lane >> 2, tg = lane & 3;
    const int p0 = pairpos(2*tg);
    const int p1 = pairpos(2*tg + 1);
#pragma unroll
    for (int mt = 0; mt < MT; mt++){
#pragma unroll
        for (int nt = 0; nt < NT; nt++){
            int cb = ncol0 + nt*8;
            float b0 = bias[cb + 2*tg], b1 = bias[cb + 2*tg + 1];
            const float* a = acc + (mt*NT+nt)*4;
            int r = row0 + mt*16 + g;
            O[r*so + cb + p0]     = to_tf32(fmaxf(a[0]+b0, 0.f));
            O[r*so + cb + p1]     = to_tf32(fmaxf(a[1]+b1, 0.f));
            O[(r+8)*so + cb + p0] = to_tf32(fmaxf(a[2]+b0, 0.f));
            O[(r+8)*so + cb + p1] = to_tf32(fmaxf(a[3]+b1, 0.f));
        }
    }
}

// ===================== prep: transpose + tf32 + pair-permute weights =====================
__global__ void prep_kernel(const float* __restrict__ w2pp, const float* __restrict__ w3pp,
                            const float* __restrict__ w2pv, const float* __restrict__ w3pv,
                            const float* __restrict__ w1o,  const float* __restrict__ w2o,
                            const float* __restrict__ w3o)
{
    int T = blockDim.x * gridDim.x, t0 = blockIdx.x * blockDim.x + threadIdx.x;
    for (int i = t0; i < 128*128; i += T){ int n = i>>7, k = i&127;
        g_W2pp[n*136 + pairpos(k)] = to_tf32(w2pp[k*128+n]); }
    for (int i = t0; i < 64*128; i += T){ int n = i>>7, k = i&127;
        g_W3pp[n*136 + pairpos(k)] = to_tf32(w3pp[k*64+n]); }
    for (int i = t0; i < 128*128; i += T){ int n = i>>7, k = i&127;
        g_W2pv[n*136 + pairpos(k)] = to_tf32(w2pv[k*128+n]); }
    for (int i = t0; i < 64*128; i += T){ int n = i>>7, k = i&127;
        g_W3pv[n*136 + pairpos(k)] = to_tf32(w3pv[k*64+n]); }
    for (int i = t0; i < 128*160; i += T){ int n = i/160, k = i - n*160;
        g_FO1[n*168 + pairpos(k)] = to_tf32(w1o[k*128+n]); }
    for (int i = t0; i < 128*128; i += T){ int n = i>>7, k = i&127;
        g_FO2[n*136 + pairpos(k)] = to_tf32(w2o[k*128+n]); }
    for (int i = t0; i < 64*128; i += T){ int n = i>>7, k = i&127;
        g_FO3[n*136 + pairpos(k)] = to_tf32(w3o[k*64+n]); }
}

// ===================== precompute: factorized first layers (fp32, pair-permuted out) ==========
__global__ void precompute_kernel(const float* __restrict__ x, const float* __restrict__ y,
                                  const float* __restrict__ w1,   const float* __restrict__ b1,
                                  const float* __restrict__ w1pv, const float* __restrict__ b1pv)
{
    __shared__ float xs[32][65];
    const int b = blockIdx.x, tid = threadIdx.x;
    for (int idx = tid; idx < 2048; idx += 256){
        int p = idx >> 6, n = idx & 63;
        xs[p][n] = x[(b*32 + p)*64 + n];
    }
    __syncthreads();
    for (int idx = tid; idx < 8192; idx += 256){
        int n = idx >> 7, h = idx & 127;
        float u = b1[h], v = 0.f, upv = b1pv[h];
#pragma unroll
        for (int p = 0; p < 32; p++){
            float xv = xs[p][n];
            u   = fmaf(xv, w1[p*128 + h], u);
            v   = fmaf(xv, w1[(32+p)*128 + h], v);
            upv = fmaf(xv, w1pv[p*128 + h], upv);
        }
        int ph = pairpos(h);
        g_Upp[(b*64+n)*128 + ph] = u;
        g_Vpp[(b*64+n)*128 + ph] = v;
        g_Upv[(b*64+n)*128 + ph] = upv;
    }
    for (int idx = tid; idx < 1792; idx += 256){
        int v = idx >> 7, h = idx & 127;
        float s = 0.f;
#pragma unroll
        for (int sv = 0; sv < 14; sv++)
            s = fmaf(y[(b*14+sv)*14 + v], w1pv[(32+sv)*128 + h], s);
        g_Vpv[(b*14+v)*128 + pairpos(h)] = s;
    }
}

// ===================== edge kernels: persistent, 512 thr, two half-CTAs =====================
// smem (bytes): W2[128x136] | W3[64x136] | BUF 2x[64x136] | b2 | b3 | part 2x256f
#define EP_W2   0
#define EP_W3   69632
#define EP_BUF  104448
#define EP_B2   174080
#define EP_B3   174592
#define EP_PT   174848
#define EP_SM   176896

__global__ __launch_bounds__(512, 1) void pp_kernel(const float* __restrict__ b2v,
                                                    const float* __restrict__ b3v)
{
    extern __shared__ char sm[];
    float* W2   = (float*)(sm + EP_W2);
    float* W3   = (float*)(sm + EP_W3);
    float* bias2= (float*)(sm + EP_B2);
    float* bias3= (float*)(sm + EP_B3);
    const int tid = threadIdx.x;
    const int half = tid >> 8, htid = tid & 255;
    const int hw = (tid >> 5) & 7, lane = tid & 31;
    const int g = lane >> 2, tg = lane & 3;
    const int rg = hw & 3, cg = hw >> 2;          // 4 row-groups x 2 col-groups (per half)
    float* BUF  = (float*)(sm + EP_BUF + half*34816);
    float* part = (float*)(sm + EP_PT  + half*1024);
    const int barid = 1 + half;

    for (int i = tid; i < 4352; i += 512) ((float4*)W2)[i] = ((const float4*)g_W2pp)[i];
    for (int i = tid; i < 2176; i += 512) ((float4*)W3)[i] = ((const float4*)g_W3pp)[i];
    if (tid < 128) bias2[tid] = b2v[tid];
    if (tid < 64)  bias3[tid] = b3v[tid];
    __syncthreads();

    const int j  = htid & 63;
    const int fo = 8*(j >> 2) + 2*(j & 3);        // pair-permuted float offset
    const int s0 = htid >> 6;

    for (int t = blockIdx.x*2 + half; t < 8192; t += gridDim.x*2){
        const int b = t >> 6, r = t & 63;
        const float* Ur = g_Upp + ((size_t)b*64 + r)*128;
        const float* Vb = g_Vpp + (size_t)b*64*128;
        // H1[s][.] = tf32(relu(U[r] + V[s])), U-fragment hoisted
        float2 u = *(const float2*)(Ur + fo);
#pragma unroll
        for (int it = 0; it < 16; it++){
            int s = s0 + it*4;
            float2 v = *(const float2*)(Vb + s*128 + fo);
            float2 h;
            h.x = to_tf32(fmaxf(u.x + v.x, 0.f));
            h.y = to_tf32(fmaxf(u.y + v.y, 0.f));
            *(float2*)(BUF + s*136 + fo) = h;
        }
        barh(barid);
        {   // layer 2: 64x128
            float acc[32];
            wgemmp<16,1,8>(BUF, 136, W2, 136, rg*16, cg*64, lane, acc);
            barh(barid);
            epi_storep<1,8>(acc, BUF, 136, rg*16, cg*64, lane, bias2);
        }
        barh(barid);
        {   // layer 3: 64x64 + self-excluded reduce
            float acc3[16];
            wgemmp<16,1,4>(BUF, 136, W3, 136, rg*16, cg*32, lane, acc3);
            int ra = rg*16 + g, rb = ra + 8;
            bool z1 = (ra == r), z2 = (rb == r);
#pragma unroll
            for (int nt = 0; nt < 4; nt++){
                int c = cg*32 + nt*8 + tg*2;
                float b0 = bias3[c], b1 = bias3[c+1];
                const float* a = acc3 + nt*4;
                float t0 = (z1 ? 0.f : fmaxf(a[0]+b0, 0.f)) + (z2 ? 0.f : fmaxf(a[2]+b0, 0.f));
                float t1 = (z1 ? 0.f : fmaxf(a[1]+b1, 0.f)) + (z2 ? 0.f : fmaxf(a[3]+b1, 0.f));
#pragma unroll
                for (int m = 4; m < 32; m <<= 1){
                    t0 += __shfl_xor_sync(0xffffffffu, t0, m);
                    t1 += __shfl_xor_sync(0xffffffffu, t1, m);
                }
                if (g == 0){ part[rg*64 + c] = t0; part[rg*64 + c + 1] = t1; }
            }
        }
        barh(barid);
        if (htid < 64){
            float ssum = part[htid] + part[64+htid] + part[128+htid] + part[192+htid];
            g_EppT[((size_t)b*64 + htid)*64 + r] = ssum;
        }
        barh(barid);
    }
}

__global__ __launch_bounds__(512, 1) void pv_kernel(const float* __restrict__ b2v,
                                                    const float* __restrict__ b3v)
{
    extern __shared__ char sm[];
    float* W2   = (float*)(sm + EP_W2);
    float* W3   = (float*)(sm + EP_W3);
    float* bias2= (float*)(sm + EP_B2);
    float* bias3= (float*)(sm + EP_B3);
    const int tid = threadIdx.x;
    const int half = tid >> 8, htid = tid & 255;
    const int hw = (tid >> 5) & 7, lane = tid & 31;
    const int g = lane >> 2, tg = lane & 3;
    const int rg = hw & 3, cg = hw >> 2;
    float* BUF = (float*)(sm + EP_BUF + half*34816);
    const int barid = 1 + half;

    for (int i = tid; i < 4352; i += 512) ((float4*)W2)[i] = ((const float4*)g_W2pv)[i];
    for (int i = tid; i < 2176; i += 512) ((float4*)W3)[i] = ((const float4*)g_W3pv)[i];
    if (tid < 128) bias2[tid] = b2v[tid];
    if (tid < 64)  bias3[tid] = b3v[tid];
    __syncthreads();

    const int j  = htid & 63;
    const int fo = 8*(j >> 2) + 2*(j & 3);
    const int s0 = htid >> 6;

    for (int t = blockIdx.x*2 + half; t < 2048; t += gridDim.x*2){
        const int b = t >> 4, grp = t & 15;       // receivers grp*4 .. grp*4+3
        const float* Ub = g_Upv + ((size_t)b*64 + grp*4)*128;
        const float* Vb = g_Vpv + (size_t)b*14*128;
        float2 u4[4];
#pragma unroll
        for (int ri = 0; ri < 4; ri++) u4[ri] = *(const float2*)(Ub + ri*128 + fo);
#pragma unroll
        for (int it = 0; it < 16; it++){
            int row = s0 + it*4;                  // 0..63 ; ri = row>>4, vv = row&15
            int ri = row >> 4, vv = row & 15;
            float2 h; h.x = 0.f; h.y = 0.f;
            if (vv < 14){
                float2 v = *(const float2*)(Vb + vv*128 + fo);
                h.x = to_tf32(fmaxf(u4[ri].x + v.x, 0.f));
                h.y = to_tf32(fmaxf(u4[ri].y + v.y, 0.f));
            }
            *(float2*)(BUF + row*136 + fo) = h;
        }
        barh(barid);
        {
            float acc[32];
            wgemmp<16,1,8>(BUF, 136, W2, 136, rg*16, cg*64, lane, acc);
            barh(barid);
            epi_storep<1,8>(acc, BUF, 136, rg*16, cg*64, lane, bias2);
        }
        barh(barid);
        {   // layer 3 + warp-local per-receiver reduce (receiver = grp*4 + rg)
            float acc3[16];
            wgemmp<16,1,4>(BUF, 136, W3, 136, rg*16, cg*32, lane, acc3);
            bool z2 = (g >= 6);                   // row vv=g+8 pad when >=14
            int recv = grp*4 + rg;
#pragma unroll
            for (int nt = 0; nt < 4; nt++){
                int c = cg*32 + nt*8 + tg*2;
                float b0 = bias3[c], b1 = bias3[c+1];
                const float* a = acc3 + nt*4;
                float t0 = fmaxf(a[0]+b0, 0.f) + (z2 ? 0.f : fmaxf(a[2]+b0, 0.f));
                float t1 = fmaxf(a[1]+b1, 0.f) + (z2 ? 0.f : fmaxf(a[3]+b1, 0.f));
#pragma unroll
                for (int m = 4; m < 32; m <<= 1){
                    t0 += __shfl_xor_sync(0xffffffffu, t0, m);
                    t1 += __shfl_xor_sync(0xffffffffu, t1, m);
                }
                if (g == 0){
                    g_EpvT[((size_t)b*64 + c)*64 + recv]     = t0;
                    g_EpvT[((size_t)b*64 + c + 1)*64 + recv] = t1;
                }
            }
        }
        barh(barid);
    }
}

// ===================== object MLP + pool + classifier: 1 graph/block =====================
#define OB_C   0
#define OB_W   43008
#define OB_H2  129024
#define OB_B1  163840
#define OB_B2  164352
#define OB_B3  164864
#define OB_FCB 165120
#define OB_PT  165152
#define OB_PL  165664
#define OB_SM  165920

__global__ __launch_bounds__(256) void obj_kernel(const float* __restrict__ x,
                                                  const float* __restrict__ b1v,
                                                  const float* __restrict__ b2v,
                                                  const float* __restrict__ b3v,
                                                  const float* __restrict__ fcw,
                                                  const float* __restrict__ fcb,
                                                  float* __restrict__ out)
{
    extern __shared__ char sm[];
    float* C    = (float*)(sm + OB_C);
    float* Wbuf = (float*)(sm + OB_W);
    float* H2   = (float*)(sm + OB_H2);
    float* H3   = (float*)(sm + OB_C);
    float* bias1  = (float*)(sm + OB_B1);
    float* bias2  = (float*)(sm + OB_B2);
    float* bias3  = (float*)(sm + OB_B3);
    float* fcbs   = (float*)(sm + OB_FCB);
    float* part   = (float*)(sm + OB_PT);
    float* pooled = (float*)(sm + OB_PL);
    const int tid = threadIdx.x, wid = tid >> 5, lane = tid & 31;
    const int g = lane >> 2, tg = lane & 3;
    const int rg = wid >> 2, cg = wid & 3;
    const int bg = blockIdx.x;

    for (int i = tid; i < 5376; i += 256) ((float4*)Wbuf)[i] = ((const float4*)g_FO1)[i];
    if (tid < 128) bias1[tid] = b1v[tid];
    if (tid < 128) bias2[tid] = b2v[tid];
    if (tid < 64)  bias3[tid] = b3v[tid];
    if (tid < 5)   fcbs[tid]  = fcb[tid];
    for (int i = tid; i < 64*80; i += 256){
        int n = i & 63, j = i >> 6;
        int k0 = 8*(j >> 2) + (j & 3);
        int fo = 8*(j >> 2) + 2*(j & 3);
        float v0, v1;
        if (k0 < 32){
            v0 = x[(bg*32 + k0)*64 + n];  v1 = x[(bg*32 + k0 + 4)*64 + n];
        } else if (k0 < 96){
            v0 = g_EppT[((size_t)bg*64 + (k0-32))*64 + n];
            v1 = g_EppT[((size_t)bg*64 + (k0-28))*64 + n];
        } else {
            v0 = g_EpvT[((size_t)bg*64 + (k0-96))*64 + n];
            v1 = g_EpvT[((size_t)bg*64 + (k0-92))*64 + n];
        }
        float2 h; h.x = to_tf32(v0); h.y = to_tf32(v1);
        *(float2*)(C + n*168 + fo) = h;
    }
    __syncthreads();
    {
        float acc[32];
        wgemmp<20,2,4>(C, 168, Wbuf, 168, rg*32, cg*32, lane, acc);
        epi_storep<2,4>(acc, H2, 136, rg*32, cg*32, lane, bias1);
    }
    __syncthreads();
    for (int i = tid; i < 4352; i += 256) ((float4*)Wbuf)[i] = ((const float4*)g_FO2)[i];
    __syncthreads();
    {
        float acc[32];
        wgemmp<16,2,4>(H2, 136, Wbuf, 136, rg*32, cg*32, lane, acc);
        __syncthreads();
        epi_storep<2,4>(acc, H3, 136, rg*32, cg*32, lane, bias2);
    }
    __syncthreads();
    for (int i = tid; i < 2176; i += 256) ((float4*)Wbuf)[i] = ((const float4*)g_FO3)[i];
    __syncthreads();
    {
        float acc[16];
        wgemmp<16,2,2>(H3, 136, Wbuf, 136, rg*32, cg*16, lane, acc);
#pragma unroll
        for (int nt = 0; nt < 2; nt++){
            int c = cg*16 + nt*8 + tg*2;
            float b0 = bias3[c], b1 = bias3[c+1];
            float t0 = 0.f, t1 = 0.f;
#pragma unroll
            for (int mt = 0; mt < 2; mt++){
                const float* a = acc + (mt*2+nt)*4;
                t0 += fmaxf(a[0]+b0, 0.f) + fmaxf(a[2]+b0, 0.f);
                t1 += fmaxf(a[1]+b1, 0.f) + fmaxf(a[3]+b1, 0.f);
            }
#pragma unroll
            for (int m = 4; m < 32; m <<= 1){
                t0 += __shfl_xor_sync(0xffffffffu, t0, m);
                t1 += __shfl_xor_sync(0xffffffffu, t1, m);
            }
            if (g == 0){ part[rg*64 + c] = t0; part[rg*64 + c + 1] = t1; }
        }
    }
    __syncthreads();
    if (tid < 64) pooled[tid] = part[tid] + part[64 + tid];
    __syncthreads();
    if (tid < 5){
        float s = fcbs[tid];
#pragma unroll 8
        for (int j = 0; j < 64; j++)
            s = fmaf(pooled[j], fcw[j*5 + tid], s);
        out[bg*5 + tid] = s;
    }
}

// ===================== launch =====================
extern "C" void kernel_launch(void* const* d_in, const int* in_sizes, int n_in,
                              void* d_out, int out_size)
{
    const float* x       = (const float*)d_in[0];
    const float* y       = (const float*)d_in[1];
    const float* fr1_w   = (const float*)d_in[2];
    const float* fr1_b   = (const float*)d_in[3];
    const float* fr2_w   = (const float*)d_in[4];
    const float* fr2_b   = (const float*)d_in[5];
    const float* fr3_w   = (const float*)d_in[6];
    const float* fr3_b   = (const float*)d_in[7];
    const float* fr1pv_w = (const float*)d_in[8];
    const float* fr1pv_b = (const float*)d_in[9];
    const float* fr2pv_w = (const float*)d_in[10];
    const float* fr2pv_b = (const float*)d_in[11];
    const float* fr3pv_w = (const float*)d_in[12];
    const float* fr3pv_b = (const float*)d_in[13];
    const float* fo1_w   = (const float*)d_in[14];
    const float* fo1_b   = (const float*)d_in[15];
    const float* fo2_w   = (const float*)d_in[16];
    const float* fo2_b   = (const float*)d_in[17];
    const float* fo3_w   = (const float*)d_in[18];
    const float* fo3_b   = (const float*)d_in[19];
    const float* fc_w    = (const float*)d_in[20];
    const float* fc_b    = (const float*)d_in[21];
    float* out = (float*)d_out;

    cudaFuncSetAttribute(pp_kernel,  cudaFuncAttributeMaxDynamicSharedMemorySize, EP_SM);
    cudaFuncSetAttribute(pv_kernel,  cudaFuncAttributeMaxDynamicSharedMemorySize, EP_SM);
    cudaFuncSetAttribute(obj_kernel, cudaFuncAttributeMaxDynamicSharedMemorySize, OB_SM);

    prep_kernel<<<64, 256>>>(fr2_w, fr3_w, fr2pv_w, fr3pv_w, fo1_w, fo2_w, fo3_w);
    precompute_kernel<<<128, 256>>>(x, y, fr1_w, fr1_b, fr1pv_w, fr1pv_b);
    pp_kernel<<<152, 512, EP_SM>>>(fr2_b, fr3_b);
    pv_kernel<<<152, 512, EP_SM>>>(fr2pv_b, fr3pv_b);
    obj_kernel<<<128, 256, OB_SM>>>(x, fo1_b, fo2_b, fo3_b, fc_w, fc_b, out);
}